// round 2
// baseline (speedup 1.0000x reference)
#include <cuda_runtime.h>
#include <cuda_bf16.h>
#include <cstdint>

// ============================================================================
// CrossAttentionBlock fused kernel (sm_100a)
//   g     = x0 @ g_w^T + g_b                [B,D]
//   theta = x1 @ th_w^T + th_b              [B,D]
//   phi   = x1 @ ph_w^T + ph_b              [B,D]
//   y_i   = sum_j exp(phi_i*theta_j)*g_j / sum_j exp(phi_i*theta_j)
//   out   = y @ W_w^T + W_b + x0            [B,C]
// One CTA per 128-row tile (128 CTAs, 256 threads). GEMMs: mma.sync m16n8k8
// tf32 (rna-converted). Attention: MUFU ex2 inner loop, no [B,D,D] tensor.
// ============================================================================

namespace {
constexpr int kB      = 16384;
constexpr int kC      = 1024;
constexpr int kD      = 128;
constexpr int kTileB  = 128;
constexpr int kNCTA   = kB / kTileB;   // 128
constexpr int kKC     = 16;            // K-chunk for projection GEMMs
constexpr int kNK     = kC / kKC;      // 64 chunks
constexpr int kXStr   = 20;            // padded smem strides
constexpr int kWStr   = 20;
constexpr int kW3Str  = 132;
constexpr float kLog2e = 1.4426950408889634f;

// smem carve (float offsets)
constexpr int TG_OFF = 0;              // [128][256] interleaved (theta*log2e, g)
constexpr int PH_OFF = 32768;          // [128][128] phi
constexpr int XS_OFF = 49152;          // [128][20]  x chunk (tf32 bits)
constexpr int WS_OFF = 51712;          // [256][20]  weight chunk (tf32 bits)
constexpr int SMEM_FLOATS = 56832;
constexpr int SMEM_BYTES  = SMEM_FLOATS * 4;  // 227328 B
}  // namespace

// y staging between attention phase and output GEMM (8 MB, L2-resident)
__device__ float g_y_scratch[kB * kD];

__device__ __forceinline__ uint32_t f2tf(float f) {
    uint32_t u;
    asm("cvt.rna.tf32.f32 %0, %1;" : "=r"(u) : "f"(f));
    return u;
}
__device__ __forceinline__ float fast_ex2(float x) {
    float r;
    asm("ex2.approx.ftz.f32 %0, %1;" : "=f"(r) : "f"(x));
    return r;
}
__device__ __forceinline__ float fast_rcp(float x) {
    float r;
    asm("rcp.approx.ftz.f32 %0, %1;" : "=f"(r) : "f"(x));
    return r;
}
__device__ __forceinline__ void mma_tf32(float c[4],
                                         const uint32_t a[4],
                                         uint32_t b0, uint32_t b1) {
    asm volatile(
        "mma.sync.aligned.m16n8k8.row.col.f32.tf32.tf32.f32 "
        "{%0,%1,%2,%3},{%4,%5,%6,%7},{%8,%9},{%0,%1,%2,%3};"
        : "+f"(c[0]), "+f"(c[1]), "+f"(c[2]), "+f"(c[3])
        : "r"(a[0]), "r"(a[1]), "r"(a[2]), "r"(a[3]), "r"(b0), "r"(b1));
}

__global__ void __launch_bounds__(256, 1)
fused_cross_attn(const float* __restrict__ x0, const float* __restrict__ x1,
                 const float* __restrict__ g_w, const float* __restrict__ g_b,
                 const float* __restrict__ th_w, const float* __restrict__ th_b,
                 const float* __restrict__ ph_w, const float* __restrict__ ph_b,
                 const float* __restrict__ Ww, const float* __restrict__ Wb,
                 float* __restrict__ out) {
    extern __shared__ float smem[];
    float* tg  = smem + TG_OFF;
    float* phs = smem + PH_OFF;
    uint32_t* Xs  = reinterpret_cast<uint32_t*>(smem + XS_OFF);
    uint32_t* Wsm = reinterpret_cast<uint32_t*>(smem + WS_OFF);

    const int tid  = threadIdx.x;
    const int lane = tid & 31;
    const int wid  = tid >> 5;
    const int row0 = blockIdx.x * kTileB;
    const int gid  = lane >> 2;  // 0..7
    const int tig  = lane & 3;   // 0..3
    const int wm   = wid >> 1;   // 0..3 (32-row slab)
    const int wn   = wid & 1;    // 0..1

    // =========================== GEMM1: g = x0 @ g_w^T ===========================
    {
        const float* xrow[2];
        const float* wrow[2];
        int sx[2], sw[2];
#pragma unroll
        for (int i = 0; i < 2; i++) {
            int idx = tid + 256 * i;
            int r = idx >> 2, c = idx & 3;
            xrow[i] = x0 + (size_t)(row0 + r) * kC + c * 4;
            wrow[i] = g_w + (size_t)r * kC + c * 4;
            sx[i] = r * kXStr + c * 4;
            sw[i] = r * kWStr + c * 4;
        }
        float4 px[2], pw[2];
#pragma unroll
        for (int i = 0; i < 2; i++) {
            px[i] = *reinterpret_cast<const float4*>(xrow[i]);
            pw[i] = *reinterpret_cast<const float4*>(wrow[i]);
        }
        float acc[2][8][4];
#pragma unroll
        for (int a = 0; a < 2; a++)
#pragma unroll
            for (int b = 0; b < 8; b++)
#pragma unroll
                for (int c = 0; c < 4; c++) acc[a][b][c] = 0.f;

#pragma unroll 1
        for (int kc = 0; kc < kNK; kc++) {
            __syncthreads();
#pragma unroll
            for (int i = 0; i < 2; i++) {
                Xs[sx[i] + 0] = f2tf(px[i].x); Xs[sx[i] + 1] = f2tf(px[i].y);
                Xs[sx[i] + 2] = f2tf(px[i].z); Xs[sx[i] + 3] = f2tf(px[i].w);
                Wsm[sw[i] + 0] = f2tf(pw[i].x); Wsm[sw[i] + 1] = f2tf(pw[i].y);
                Wsm[sw[i] + 2] = f2tf(pw[i].z); Wsm[sw[i] + 3] = f2tf(pw[i].w);
            }
            __syncthreads();
            if (kc + 1 < kNK) {
                int off = (kc + 1) * kKC;
#pragma unroll
                for (int i = 0; i < 2; i++) {
                    px[i] = *reinterpret_cast<const float4*>(xrow[i] + off);
                    pw[i] = *reinterpret_cast<const float4*>(wrow[i] + off);
                }
            }
#pragma unroll
            for (int ks = 0; ks < 2; ks++) {
                int k = ks * 8;
                uint32_t a[2][4];
#pragma unroll
                for (int mt = 0; mt < 2; mt++) {
                    int rb = (wm * 32 + mt * 16 + gid) * kXStr + k + tig;
                    a[mt][0] = Xs[rb];
                    a[mt][1] = Xs[rb + 8 * kXStr];
                    a[mt][2] = Xs[rb + 4];
                    a[mt][3] = Xs[rb + 8 * kXStr + 4];
                }
#pragma unroll
                for (int nt = 0; nt < 8; nt++) {
                    int nb = (wn * 64 + nt * 8 + gid) * kWStr + k + tig;
                    uint32_t b0 = Wsm[nb];
                    uint32_t b1 = Wsm[nb + 4];
                    mma_tf32(acc[0][nt], a[0], b0, b1);
                    mma_tf32(acc[1][nt], a[1], b0, b1);
                }
            }
        }
        // epilogue: g into tg[r][2n+1]
#pragma unroll
        for (int mt = 0; mt < 2; mt++)
#pragma unroll
            for (int nt = 0; nt < 8; nt++)
#pragma unroll
                for (int ci = 0; ci < 4; ci++) {
                    int r = wm * 32 + mt * 16 + gid + ((ci >= 2) ? 8 : 0);
                    int n = wn * 64 + nt * 8 + tig * 2 + (ci & 1);
                    tg[r * 256 + 2 * n + 1] = acc[mt][nt][ci] + g_b[n];
                }
    }

    // ================= GEMM2: [theta; phi] = x1 @ [th_w; ph_w]^T =================
    {
        const float* xrow[2];
        const float* wrow[4];
        int sx[2], sw[4];
#pragma unroll
        for (int i = 0; i < 2; i++) {
            int idx = tid + 256 * i;
            int r = idx >> 2, c = idx & 3;
            xrow[i] = x1 + (size_t)(row0 + r) * kC + c * 4;
            sx[i] = r * kXStr + c * 4;
        }
#pragma unroll
        for (int i = 0; i < 4; i++) {
            int idx = tid + 256 * i;
            int r = idx >> 2, c = idx & 3;  // r in 0..255
            wrow[i] = (r < 128) ? (th_w + (size_t)r * kC + c * 4)
                                : (ph_w + (size_t)(r - 128) * kC + c * 4);
            sw[i] = r * kWStr + c * 4;
        }
        float4 px[2], pw[4];
#pragma unroll
        for (int i = 0; i < 2; i++) px[i] = *reinterpret_cast<const float4*>(xrow[i]);
#pragma unroll
        for (int i = 0; i < 4; i++) pw[i] = *reinterpret_cast<const float4*>(wrow[i]);

        float acc[2][16][4];
#pragma unroll
        for (int a = 0; a < 2; a++)
#pragma unroll
            for (int b = 0; b < 16; b++)
#pragma unroll
                for (int c = 0; c < 4; c++) acc[a][b][c] = 0.f;

#pragma unroll 1
        for (int kc = 0; kc < kNK; kc++) {
            __syncthreads();
#pragma unroll
            for (int i = 0; i < 2; i++) {
                Xs[sx[i] + 0] = f2tf(px[i].x); Xs[sx[i] + 1] = f2tf(px[i].y);
                Xs[sx[i] + 2] = f2tf(px[i].z); Xs[sx[i] + 3] = f2tf(px[i].w);
            }
#pragma unroll
            for (int i = 0; i < 4; i++) {
                Wsm[sw[i] + 0] = f2tf(pw[i].x); Wsm[sw[i] + 1] = f2tf(pw[i].y);
                Wsm[sw[i] + 2] = f2tf(pw[i].z); Wsm[sw[i] + 3] = f2tf(pw[i].w);
            }
            __syncthreads();
            if (kc + 1 < kNK) {
                int off = (kc + 1) * kKC;
#pragma unroll
                for (int i = 0; i < 2; i++)
                    px[i] = *reinterpret_cast<const float4*>(xrow[i] + off);
#pragma unroll
                for (int i = 0; i < 4; i++)
                    pw[i] = *reinterpret_cast<const float4*>(wrow[i] + off);
            }
#pragma unroll
            for (int ks = 0; ks < 2; ks++) {
                int k = ks * 8;
                uint32_t a[2][4];
#pragma unroll
                for (int mt = 0; mt < 2; mt++) {
                    int rb = (wm * 32 + mt * 16 + gid) * kXStr + k + tig;
                    a[mt][0] = Xs[rb];
                    a[mt][1] = Xs[rb + 8 * kXStr];
                    a[mt][2] = Xs[rb + 4];
                    a[mt][3] = Xs[rb + 8 * kXStr + 4];
                }
#pragma unroll
                for (int nt = 0; nt < 16; nt++) {
                    int nb = (wn * 128 + nt * 8 + gid) * kWStr + k + tig;
                    uint32_t b0 = Wsm[nb];
                    uint32_t b1 = Wsm[nb + 4];
                    mma_tf32(acc[0][nt], a[0], b0, b1);
                    mma_tf32(acc[1][nt], a[1], b0, b1);
                }
            }
        }
        // epilogue: wn==0 -> theta*log2e into tg[r][2n]; wn==1 -> phi into phs
#pragma unroll
        for (int mt = 0; mt < 2; mt++)
#pragma unroll
            for (int nt = 0; nt < 16; nt++)
#pragma unroll
                for (int ci = 0; ci < 4; ci++) {
                    int r = wm * 32 + mt * 16 + gid + ((ci >= 2) ? 8 : 0);
                    int nloc = nt * 8 + tig * 2 + (ci & 1);  // 0..127 within half
                    if (wn == 0) {
                        tg[r * 256 + 2 * nloc] = (acc[mt][nt][ci] + th_b[nloc]) * kLog2e;
                    } else {
                        phs[r * 128 + nloc] = acc[mt][nt][ci] + ph_b[nloc];
                    }
                }
    }

    __syncthreads();

    // ============== Attention: y = softmax(phi theta^T) g (no materialize) ==============
    {
#pragma unroll 1
        for (int rl = 0; rl < 16; rl++) {
            int r = wid * 16 + rl;
            const float* pr = phs + r * 128;
            float p0 = pr[lane], p1 = pr[lane + 32], p2 = pr[lane + 64], p3 = pr[lane + 96];
            const float2* tgr = reinterpret_cast<const float2*>(tg + r * 256);
            float n0 = 0.f, n1 = 0.f, n2 = 0.f, n3 = 0.f;
            float d0 = 0.f, d1 = 0.f, d2 = 0.f, d3 = 0.f;
#pragma unroll 8
            for (int j = 0; j < 128; j++) {
                float2 t = tgr[j];  // (theta_j*log2e, g_j) broadcast
                float e0 = fast_ex2(p0 * t.x);
                float e1 = fast_ex2(p1 * t.x);
                float e2 = fast_ex2(p2 * t.x);
                float e3 = fast_ex2(p3 * t.x);
                d0 += e0; d1 += e1; d2 += e2; d3 += e3;
                n0 = fmaf(e0, t.y, n0);
                n1 = fmaf(e1, t.y, n1);
                n2 = fmaf(e2, t.y, n2);
                n3 = fmaf(e3, t.y, n3);
            }
            float* yr = g_y_scratch + (size_t)(row0 + r) * kD;
            yr[lane]      = __uint_as_float(f2tf(n0 * fast_rcp(d0)));
            yr[lane + 32] = __uint_as_float(f2tf(n1 * fast_rcp(d1)));
            yr[lane + 64] = __uint_as_float(f2tf(n2 * fast_rcp(d2)));
            yr[lane + 96] = __uint_as_float(f2tf(n3 * fast_rcp(d3)));
        }
    }

    __syncthreads();  // smem now free for reuse

    // ====================== GEMM3: out = y @ W_w^T + W_b + x0 ======================
    {
        uint32_t* W3 = reinterpret_cast<uint32_t*>(smem);  // [256][132] tf32 bits
        const uint32_t* ybase = reinterpret_cast<const uint32_t*>(g_y_scratch);
#pragma unroll 1
        for (int nc = 0; nc < 4; nc++) {
            __syncthreads();
            // stage W_w rows [nc*256, nc*256+256), 128 cols each
#pragma unroll
            for (int i = 0; i < 32; i++) {
                int idx = tid + 256 * i;  // 0..8191
                int rr = idx >> 5;        // 0..255
                int cc = idx & 31;        // 0..31 (float4 index)
                float4 v = *reinterpret_cast<const float4*>(
                    Ww + (size_t)(nc * 256 + rr) * kD + cc * 4);
                int so = rr * kW3Str + cc * 4;
                W3[so + 0] = f2tf(v.x); W3[so + 1] = f2tf(v.y);
                W3[so + 2] = f2tf(v.z); W3[so + 3] = f2tf(v.w);
            }
            __syncthreads();

            float acc[2][16][4];
#pragma unroll
            for (int a = 0; a < 2; a++)
#pragma unroll
                for (int b = 0; b < 16; b++)
#pragma unroll
                    for (int c = 0; c < 4; c++) acc[a][b][c] = 0.f;

#pragma unroll 4
            for (int ks = 0; ks < 16; ks++) {
                int k = ks * 8;
                uint32_t a[2][4];
#pragma unroll
                for (int mt = 0; mt < 2; mt++) {
                    const uint32_t* yb =
                        ybase + (size_t)(row0 + wm * 32 + mt * 16 + gid) * kD + k + tig;
                    a[mt][0] = yb[0];
                    a[mt][1] = yb[8 * kD];
                    a[mt][2] = yb[4];
                    a[mt][3] = yb[8 * kD + 4];
                }
#pragma unroll
                for (int nt = 0; nt < 16; nt++) {
                    int nb = (wn * 128 + nt * 8 + gid) * kW3Str + k + tig;
                    uint32_t b0 = W3[nb];
                    uint32_t b1 = W3[nb + 4];
                    mma_tf32(acc[0][nt], a[0], b0, b1);
                    mma_tf32(acc[1][nt], a[1], b0, b1);
                }
            }
            // epilogue: + W_b + x0 residual, write out
#pragma unroll
            for (int mt = 0; mt < 2; mt++)
#pragma unroll
                for (int nt = 0; nt < 16; nt++)
#pragma unroll
                    for (int pair = 0; pair < 2; pair++) {
                        int r = wm * 32 + mt * 16 + gid + pair * 8;
                        int n = nc * 256 + wn * 128 + nt * 8 + tig * 2;
                        float2 xx = *reinterpret_cast<const float2*>(
                            x0 + (size_t)(row0 + r) * kC + n);
                        float2 o;
                        o.x = acc[mt][nt][pair * 2 + 0] + Wb[n] + xx.x;
                        o.y = acc[mt][nt][pair * 2 + 1] + Wb[n + 1] + xx.y;
                        *reinterpret_cast<float2*>(out + (size_t)(row0 + r) * kC + n) = o;
                    }
        }
    }
}

extern "C" void kernel_launch(void* const* d_in, const int* in_sizes, int n_in,
                              void* d_out, int out_size) {
    (void)in_sizes; (void)n_in; (void)out_size;
    cudaFuncSetAttribute(fused_cross_attn,
                         cudaFuncAttributeMaxDynamicSharedMemorySize, SMEM_BYTES);
    fused_cross_attn<<<kNCTA, 256, SMEM_BYTES>>>(
        (const float*)d_in[0], (const float*)d_in[1],
        (const float*)d_in[2], (const float*)d_in[3],
        (const float*)d_in[4], (const float*)d_in[5],
        (const float*)d_in[6], (const float*)d_in[7],
        (const float*)d_in[8], (const float*)d_in[9],
        (float*)d_out);
}

// round 3
// speedup vs baseline: 1.2102x; 1.2102x over previous
#include <cuda_runtime.h>
#include <cuda_bf16.h>
#include <cstdint>

// ============================================================================
// CrossAttentionBlock — 3-kernel split (sm_100a)
//   K1: g = x0@g_w^T+g_b ; th = (x1@th_w^T+th_b)*log2e ; ph = x1@ph_w^T+ph_b
//   K2: y_i = sum_j 2^(ph_i*th_j) g_j / sum_j 2^(ph_i*th_j)   (MUFU-bound)
//   K3: out = y@W_w^T + W_b + x0
// ============================================================================

namespace {
constexpr int kB   = 16384;
constexpr int kC   = 1024;
constexpr int kD   = 128;
constexpr int kXStr  = 20;    // smem stride for K1 tiles (conflict-free)
constexpr int kW3Str = 132;   // smem stride for K3 W tile
constexpr float kLog2e = 1.4426950408889634f;
constexpr int kK3Smem = 128 * kW3Str * 4;  // 67584 B
}  // namespace

// inter-kernel scratch (32 MB total)
__device__ float g_glob[kB * kD];
__device__ float th_glob[kB * kD];   // pre-scaled by log2e
__device__ float ph_glob[kB * kD];
__device__ float y_glob[kB * kD];    // stored as tf32 bit patterns

__device__ __forceinline__ uint32_t f2tf(float f) {
    uint32_t u;
    asm("cvt.rna.tf32.f32 %0, %1;" : "=r"(u) : "f"(f));
    return u;
}
__device__ __forceinline__ float fast_ex2(float x) {
    float r;
    asm("ex2.approx.ftz.f32 %0, %1;" : "=f"(r) : "f"(x));
    return r;
}
__device__ __forceinline__ float fast_rcp(float x) {
    float r;
    asm("rcp.approx.ftz.f32 %0, %1;" : "=f"(r) : "f"(x));
    return r;
}
__device__ __forceinline__ void mma_tf32(float c[4],
                                         const uint32_t a[4],
                                         uint32_t b0, uint32_t b1) {
    asm volatile(
        "mma.sync.aligned.m16n8k8.row.col.f32.tf32.tf32.f32 "
        "{%0,%1,%2,%3},{%4,%5,%6,%7},{%8,%9},{%0,%1,%2,%3};"
        : "+f"(c[0]), "+f"(c[1]), "+f"(c[2]), "+f"(c[3])
        : "r"(a[0]), "r"(a[1]), "r"(a[2]), "r"(a[3]), "r"(b0), "r"(b1));
}
__device__ __forceinline__ void sts_tf4(uint32_t* dst, float4 v) {
    uint4 u;
    u.x = f2tf(v.x); u.y = f2tf(v.y); u.z = f2tf(v.z); u.w = f2tf(v.w);
    *reinterpret_cast<uint4*>(dst) = u;
}

// ========================= K1: projection GEMMs =========================
// grid (128 B-tiles, 3 heads), 256 thr. Tile 128x128, K=1024 chunked by 16,
// ping-pong smem, one sync per chunk.
__global__ void __launch_bounds__(256, 2)
proj_kernel(const float* __restrict__ x0, const float* __restrict__ x1,
            const float* __restrict__ g_w, const float* __restrict__ g_b,
            const float* __restrict__ th_w, const float* __restrict__ th_b,
            const float* __restrict__ ph_w, const float* __restrict__ ph_b) {
    __shared__ uint32_t Xs[2][128 * kXStr];
    __shared__ uint32_t Ws[2][128 * kXStr];

    const int tid  = threadIdx.x;
    const int lane = tid & 31;
    const int wid  = tid >> 5;
    const int gid  = lane >> 2;
    const int tig  = lane & 3;
    const int wm   = wid >> 1;
    const int wn   = wid & 1;
    const int row0 = blockIdx.x * 128;
    const int by   = blockIdx.y;

    const float* A = (by == 0) ? x0 : x1;
    const float* W = (by == 0) ? g_w : (by == 1) ? th_w : ph_w;
    const float* bias = (by == 0) ? g_b : (by == 1) ? th_b : ph_b;
    float* outp = (by == 0) ? g_glob : (by == 1) ? th_glob : ph_glob;
    const float scale = (by == 1) ? kLog2e : 1.0f;

    // per-thread load slots: 2 float4 for A, 2 for W (128 rows x 16 cols each)
    const float* aptr[2];
    const float* wptr[2];
    int soff[2];
#pragma unroll
    for (int i = 0; i < 2; i++) {
        int idx = tid + 256 * i;
        int r = idx >> 2, c = idx & 3;
        aptr[i] = A + (size_t)(row0 + r) * kC + c * 4;
        wptr[i] = W + (size_t)r * kC + c * 4;
        soff[i] = r * kXStr + c * 4;
    }

    float4 pa[2], pw[2];
#pragma unroll
    for (int i = 0; i < 2; i++) {
        pa[i] = *reinterpret_cast<const float4*>(aptr[i]);
        pw[i] = *reinterpret_cast<const float4*>(wptr[i]);
    }
#pragma unroll
    for (int i = 0; i < 2; i++) {
        sts_tf4(&Xs[0][soff[i]], pa[i]);
        sts_tf4(&Ws[0][soff[i]], pw[i]);
    }
    __syncthreads();

    float acc[2][8][4];
#pragma unroll
    for (int a = 0; a < 2; a++)
#pragma unroll
        for (int b = 0; b < 8; b++)
#pragma unroll
            for (int c = 0; c < 4; c++) acc[a][b][c] = 0.f;

#pragma unroll 1
    for (int kc = 0; kc < 64; kc++) {
        const int buf = kc & 1;
        if (kc + 1 < 64) {
            int off = (kc + 1) * 16;
#pragma unroll
            for (int i = 0; i < 2; i++) {
                pa[i] = *reinterpret_cast<const float4*>(aptr[i] + off);
                pw[i] = *reinterpret_cast<const float4*>(wptr[i] + off);
            }
        }
#pragma unroll
        for (int ks = 0; ks < 2; ks++) {
            int k = ks * 8;
            uint32_t a[2][4];
#pragma unroll
            for (int mt = 0; mt < 2; mt++) {
                int rb = (wm * 32 + mt * 16 + gid) * kXStr + k + tig;
                a[mt][0] = Xs[buf][rb];
                a[mt][1] = Xs[buf][rb + 8 * kXStr];
                a[mt][2] = Xs[buf][rb + 4];
                a[mt][3] = Xs[buf][rb + 8 * kXStr + 4];
            }
#pragma unroll
            for (int nt = 0; nt < 8; nt++) {
                int nb = (wn * 64 + nt * 8 + gid) * kXStr + k + tig;
                uint32_t b0 = Ws[buf][nb];
                uint32_t b1 = Ws[buf][nb + 4];
                mma_tf32(acc[0][nt], a[0], b0, b1);
                mma_tf32(acc[1][nt], a[1], b0, b1);
            }
        }
        if (kc + 1 < 64) {
#pragma unroll
            for (int i = 0; i < 2; i++) {
                sts_tf4(&Xs[buf ^ 1][soff[i]], pa[i]);
                sts_tf4(&Ws[buf ^ 1][soff[i]], pw[i]);
            }
        }
        __syncthreads();
    }

#pragma unroll
    for (int mt = 0; mt < 2; mt++)
#pragma unroll
        for (int nt = 0; nt < 8; nt++)
#pragma unroll
            for (int ci = 0; ci < 4; ci++) {
                int r = wm * 32 + mt * 16 + gid + ((ci >= 2) ? 8 : 0);
                int n = wn * 64 + nt * 8 + tig * 2 + (ci & 1);
                outp[(size_t)(row0 + r) * kD + n] = (acc[mt][nt][ci] + bias[n]) * scale;
            }
}

// ========================= K2: attention (MUFU-bound) =========================
// grid 2048 CTAs x 256 thr; 1 row per warp. theta pre-scaled by log2e.
__global__ void __launch_bounds__(256)
attn_kernel() {
    __shared__ float tgs[8][256];  // per-warp (theta*log2e, g) interleaved

    const int lane = threadIdx.x & 31;
    const int wid  = threadIdx.x >> 5;
    const int r    = blockIdx.x * 8 + wid;

    // stage interleaved (theta, g) row into this warp's smem slot
    {
        float4 t4 = *reinterpret_cast<const float4*>(th_glob + (size_t)r * kD + lane * 4);
        float4 g4 = *reinterpret_cast<const float4*>(g_glob + (size_t)r * kD + lane * 4);
        float4* d = reinterpret_cast<float4*>(&tgs[wid][lane * 8]);
        d[0] = make_float4(t4.x, g4.x, t4.y, g4.y);
        d[1] = make_float4(t4.z, g4.z, t4.w, g4.w);
    }
    const float* pr = ph_glob + (size_t)r * kD;
    float p0 = pr[lane], p1 = pr[lane + 32], p2 = pr[lane + 64], p3 = pr[lane + 96];
    __syncwarp();

    const float2* tgr = reinterpret_cast<const float2*>(tgs[wid]);
    float n0 = 0.f, n1 = 0.f, n2 = 0.f, n3 = 0.f;
    float d0 = 0.f, d1 = 0.f, d2 = 0.f, d3 = 0.f;
#pragma unroll 8
    for (int j = 0; j < kD; j++) {
        float2 t = tgr[j];
        float e0 = fast_ex2(p0 * t.x);
        float e1 = fast_ex2(p1 * t.x);
        float e2 = fast_ex2(p2 * t.x);
        float e3 = fast_ex2(p3 * t.x);
        d0 += e0; d1 += e1; d2 += e2; d3 += e3;
        n0 = fmaf(e0, t.y, n0);
        n1 = fmaf(e1, t.y, n1);
        n2 = fmaf(e2, t.y, n2);
        n3 = fmaf(e3, t.y, n3);
    }
    float* yr = y_glob + (size_t)r * kD;
    yr[lane]      = __uint_as_float(f2tf(n0 * fast_rcp(d0)));
    yr[lane + 32] = __uint_as_float(f2tf(n1 * fast_rcp(d1)));
    yr[lane + 64] = __uint_as_float(f2tf(n2 * fast_rcp(d2)));
    yr[lane + 96] = __uint_as_float(f2tf(n3 * fast_rcp(d3)));
}

// ========================= K3: out = y@W_w^T + W_b + x0 =========================
// grid (128 B-tiles, 8 N-tiles), 256 thr. Tile 128x128, K=128 single pass.
__global__ void __launch_bounds__(256, 2)
out_kernel(const float* __restrict__ x0, const float* __restrict__ Ww,
           const float* __restrict__ Wb, float* __restrict__ out) {
    extern __shared__ uint32_t W3[];  // [128][132] tf32 bits

    const int tid  = threadIdx.x;
    const int lane = tid & 31;
    const int wid  = tid >> 5;
    const int gid  = lane >> 2;
    const int tig  = lane & 3;
    const int wm   = wid >> 1;
    const int wn   = wid & 1;
    const int row0 = blockIdx.x * 128;
    const int col0 = blockIdx.y * 128;

    // stage W rows [col0, col0+128) x 128 cols (tf32)
#pragma unroll
    for (int i = 0; i < 16; i++) {
        int idx = tid + 256 * i;     // 0..4095
        int rr = idx >> 5;           // 0..127
        int cc = idx & 31;           // float4 index 0..31
        float4 v = *reinterpret_cast<const float4*>(
            Ww + (size_t)(col0 + rr) * kD + cc * 4);
        sts_tf4(&W3[rr * kW3Str + cc * 4], v);
    }
    __syncthreads();

    float acc[2][8][4];
#pragma unroll
    for (int a = 0; a < 2; a++)
#pragma unroll
        for (int b = 0; b < 8; b++)
#pragma unroll
            for (int c = 0; c < 4; c++) acc[a][b][c] = 0.f;

    const uint32_t* ybase = reinterpret_cast<const uint32_t*>(y_glob);
#pragma unroll 4
    for (int ks = 0; ks < 16; ks++) {
        int k = ks * 8;
        uint32_t a[2][4];
#pragma unroll
        for (int mt = 0; mt < 2; mt++) {
            const uint32_t* yb =
                ybase + (size_t)(row0 + wm * 32 + mt * 16 + gid) * kD + k + tig;
            a[mt][0] = yb[0];
            a[mt][1] = yb[8 * kD];
            a[mt][2] = yb[4];
            a[mt][3] = yb[8 * kD + 4];
        }
#pragma unroll
        for (int nt = 0; nt < 8; nt++) {
            int nb = (wn * 64 + nt * 8 + gid) * kW3Str + k + tig;
            uint32_t b0 = W3[nb];
            uint32_t b1 = W3[nb + 4];
            mma_tf32(acc[0][nt], a[0], b0, b1);
            mma_tf32(acc[1][nt], a[1], b0, b1);
        }
    }

    // epilogue: + W_b + x0 residual
#pragma unroll
    for (int mt = 0; mt < 2; mt++)
#pragma unroll
        for (int nt = 0; nt < 8; nt++)
#pragma unroll
            for (int pair = 0; pair < 2; pair++) {
                int r = wm * 32 + mt * 16 + gid + pair * 8;
                int n = col0 + wn * 64 + nt * 8 + tig * 2;
                float2 xx = *reinterpret_cast<const float2*>(
                    x0 + (size_t)(row0 + r) * kC + n);
                float2 o;
                o.x = acc[mt][nt][pair * 2 + 0] + Wb[n] + xx.x;
                o.y = acc[mt][nt][pair * 2 + 1] + Wb[n + 1] + xx.y;
                *reinterpret_cast<float2*>(out + (size_t)(row0 + r) * kC + n) = o;
            }
}

extern "C" void kernel_launch(void* const* d_in, const int* in_sizes, int n_in,
                              void* d_out, int out_size) {
    (void)in_sizes; (void)n_in; (void)out_size;
    const float* x0   = (const float*)d_in[0];
    const float* x1   = (const float*)d_in[1];
    const float* g_w  = (const float*)d_in[2];
    const float* g_b  = (const float*)d_in[3];
    const float* th_w = (const float*)d_in[4];
    const float* th_b = (const float*)d_in[5];
    const float* ph_w = (const float*)d_in[6];
    const float* ph_b = (const float*)d_in[7];
    const float* Ww   = (const float*)d_in[8];
    const float* Wb   = (const float*)d_in[9];
    float* out = (float*)d_out;

    cudaFuncSetAttribute(out_kernel,
                         cudaFuncAttributeMaxDynamicSharedMemorySize, kK3Smem);

    proj_kernel<<<dim3(128, 3), 256>>>(x0, x1, g_w, g_b, th_w, th_b, ph_w, ph_b);
    attn_kernel<<<2048, 256>>>();
    out_kernel<<<dim3(128, 8), 256, kK3Smem>>>(x0, Ww, Wb, out);
}

// round 4
// speedup vs baseline: 1.2125x; 1.0019x over previous
#include <cuda_runtime.h>
#include <cuda_bf16.h>
#include <cstdint>

// ============================================================================
// CrossAttentionBlock — 3-kernel split (sm_100a)
//   K1: g = x0@g_w^T+g_b ; th = (x1@th_w^T+th_b)*log2e ; ph = x1@ph_w^T+ph_b
//   K2: y_i = sum_j 2^(ph_i*th_j) g_j / sum_j 2^(ph_i*th_j)   (MUFU-bound)
//   K3: out = y@W_w^T + W_b + x0
// ============================================================================

namespace {
constexpr int kB   = 16384;
constexpr int kC   = 1024;
constexpr int kD   = 128;
constexpr int kXStr  = 20;    // smem stride for K1 tiles (conflict-free)
constexpr int kW3Str = 132;   // smem stride for K3 W tile
constexpr float kLog2e = 1.4426950408889634f;
constexpr int kK3Smem = 128 * kW3Str * 4;  // 67584 B
}  // namespace

// inter-kernel scratch (32 MB total)
__device__ float g_glob[kB * kD];
__device__ float th_glob[kB * kD];   // pre-scaled by log2e
__device__ float ph_glob[kB * kD];
__device__ float y_glob[kB * kD];    // stored as tf32 bit patterns

__device__ __forceinline__ uint32_t f2tf(float f) {
    uint32_t u;
    asm("cvt.rna.tf32.f32 %0, %1;" : "=r"(u) : "f"(f));
    return u;
}
__device__ __forceinline__ float fast_ex2(float x) {
    float r;
    asm("ex2.approx.ftz.f32 %0, %1;" : "=f"(r) : "f"(x));
    return r;
}
__device__ __forceinline__ float fast_rcp(float x) {
    float r;
    asm("rcp.approx.ftz.f32 %0, %1;" : "=f"(r) : "f"(x));
    return r;
}
__device__ __forceinline__ void mma_tf32(float c[4],
                                         const uint32_t a[4],
                                         uint32_t b0, uint32_t b1) {
    asm volatile(
        "mma.sync.aligned.m16n8k8.row.col.f32.tf32.tf32.f32 "
        "{%0,%1,%2,%3},{%4,%5,%6,%7},{%8,%9},{%0,%1,%2,%3};"
        : "+f"(c[0]), "+f"(c[1]), "+f"(c[2]), "+f"(c[3])
        : "r"(a[0]), "r"(a[1]), "r"(a[2]), "r"(a[3]), "r"(b0), "r"(b1));
}
__device__ __forceinline__ void sts_tf4(uint32_t* dst, float4 v) {
    uint4 u;
    u.x = f2tf(v.x); u.y = f2tf(v.y); u.z = f2tf(v.z); u.w = f2tf(v.w);
    *reinterpret_cast<uint4*>(dst) = u;
}

// ========================= K1: projection GEMMs =========================
// grid (128 B-tiles, 3 heads), 256 thr. Tile 128x128, K=1024 chunked by 16,
// ping-pong smem, one sync per chunk.
__global__ void __launch_bounds__(256, 2)
proj_kernel(const float* __restrict__ x0, const float* __restrict__ x1,
            const float* __restrict__ g_w, const float* __restrict__ g_b,
            const float* __restrict__ th_w, const float* __restrict__ th_b,
            const float* __restrict__ ph_w, const float* __restrict__ ph_b) {
    __shared__ uint32_t Xs[2][128 * kXStr];
    __shared__ uint32_t Ws[2][128 * kXStr];

    const int tid  = threadIdx.x;
    const int lane = tid & 31;
    const int wid  = tid >> 5;
    const int gid  = lane >> 2;
    const int tig  = lane & 3;
    const int wm   = wid >> 1;
    const int wn   = wid & 1;
    const int row0 = blockIdx.x * 128;
    const int by   = blockIdx.y;

    const float* A = (by == 0) ? x0 : x1;
    const float* W = (by == 0) ? g_w : (by == 1) ? th_w : ph_w;
    const float* bias = (by == 0) ? g_b : (by == 1) ? th_b : ph_b;
    float* outp = (by == 0) ? g_glob : (by == 1) ? th_glob : ph_glob;
    const float scale = (by == 1) ? kLog2e : 1.0f;

    // per-thread load slots: 2 float4 for A, 2 for W (128 rows x 16 cols each)
    const float* aptr[2];
    const float* wptr[2];
    int soff[2];
#pragma unroll
    for (int i = 0; i < 2; i++) {
        int idx = tid + 256 * i;
        int r = idx >> 2, c = idx & 3;
        aptr[i] = A + (size_t)(row0 + r) * kC + c * 4;
        wptr[i] = W + (size_t)r * kC + c * 4;
        soff[i] = r * kXStr + c * 4;
    }

    float4 pa[2], pw[2];
#pragma unroll
    for (int i = 0; i < 2; i++) {
        pa[i] = *reinterpret_cast<const float4*>(aptr[i]);
        pw[i] = *reinterpret_cast<const float4*>(wptr[i]);
    }
#pragma unroll
    for (int i = 0; i < 2; i++) {
        sts_tf4(&Xs[0][soff[i]], pa[i]);
        sts_tf4(&Ws[0][soff[i]], pw[i]);
    }
    __syncthreads();

    float acc[2][8][4];
#pragma unroll
    for (int a = 0; a < 2; a++)
#pragma unroll
        for (int b = 0; b < 8; b++)
#pragma unroll
            for (int c = 0; c < 4; c++) acc[a][b][c] = 0.f;

#pragma unroll 1
    for (int kc = 0; kc < 64; kc++) {
        const int buf = kc & 1;
        if (kc + 1 < 64) {
            int off = (kc + 1) * 16;
#pragma unroll
            for (int i = 0; i < 2; i++) {
                pa[i] = *reinterpret_cast<const float4*>(aptr[i] + off);
                pw[i] = *reinterpret_cast<const float4*>(wptr[i] + off);
            }
        }
#pragma unroll
        for (int ks = 0; ks < 2; ks++) {
            int k = ks * 8;
            uint32_t a[2][4];
#pragma unroll
            for (int mt = 0; mt < 2; mt++) {
                int rb = (wm * 32 + mt * 16 + gid) * kXStr + k + tig;
                a[mt][0] = Xs[buf][rb];
                a[mt][1] = Xs[buf][rb + 8 * kXStr];
                a[mt][2] = Xs[buf][rb + 4];
                a[mt][3] = Xs[buf][rb + 8 * kXStr + 4];
            }
#pragma unroll
            for (int nt = 0; nt < 8; nt++) {
                int nb = (wn * 64 + nt * 8 + gid) * kXStr + k + tig;
                uint32_t b0 = Ws[buf][nb];
                uint32_t b1 = Ws[buf][nb + 4];
                mma_tf32(acc[0][nt], a[0], b0, b1);
                mma_tf32(acc[1][nt], a[1], b0, b1);
            }
        }
        if (kc + 1 < 64) {
#pragma unroll
            for (int i = 0; i < 2; i++) {
                sts_tf4(&Xs[buf ^ 1][soff[i]], pa[i]);
                sts_tf4(&Ws[buf ^ 1][soff[i]], pw[i]);
            }
        }
        __syncthreads();
    }

#pragma unroll
    for (int mt = 0; mt < 2; mt++)
#pragma unroll
        for (int nt = 0; nt < 8; nt++)
#pragma unroll
            for (int ci = 0; ci < 4; ci++) {
                int r = wm * 32 + mt * 16 + gid + ((ci >= 2) ? 8 : 0);
                int n = wn * 64 + nt * 8 + tig * 2 + (ci & 1);
                outp[(size_t)(row0 + r) * kD + n] = (acc[mt][nt][ci] + bias[n]) * scale;
            }
}

// ========================= K2: attention (MUFU-bound) =========================
// grid 2048 CTAs x 256 thr; 1 row per warp. theta pre-scaled by log2e.
__global__ void __launch_bounds__(256)
attn_kernel() {
    __shared__ float tgs[8][256];  // per-warp (theta*log2e, g) interleaved

    const int lane = threadIdx.x & 31;
    const int wid  = threadIdx.x >> 5;
    const int r    = blockIdx.x * 8 + wid;

    // stage interleaved (theta, g) row into this warp's smem slot
    {
        float4 t4 = *reinterpret_cast<const float4*>(th_glob + (size_t)r * kD + lane * 4);
        float4 g4 = *reinterpret_cast<const float4*>(g_glob + (size_t)r * kD + lane * 4);
        float4* d = reinterpret_cast<float4*>(&tgs[wid][lane * 8]);
        d[0] = make_float4(t4.x, g4.x, t4.y, g4.y);
        d[1] = make_float4(t4.z, g4.z, t4.w, g4.w);
    }
    const float* pr = ph_glob + (size_t)r * kD;
    float p0 = pr[lane], p1 = pr[lane + 32], p2 = pr[lane + 64], p3 = pr[lane + 96];
    __syncwarp();

    const float2* tgr = reinterpret_cast<const float2*>(tgs[wid]);
    float n0 = 0.f, n1 = 0.f, n2 = 0.f, n3 = 0.f;
    float d0 = 0.f, d1 = 0.f, d2 = 0.f, d3 = 0.f;
#pragma unroll 8
    for (int j = 0; j < kD; j++) {
        float2 t = tgr[j];
        float e0 = fast_ex2(p0 * t.x);
        float e1 = fast_ex2(p1 * t.x);
        float e2 = fast_ex2(p2 * t.x);
        float e3 = fast_ex2(p3 * t.x);
        d0 += e0; d1 += e1; d2 += e2; d3 += e3;
        n0 = fmaf(e0, t.y, n0);
        n1 = fmaf(e1, t.y, n1);
        n2 = fmaf(e2, t.y, n2);
        n3 = fmaf(e3, t.y, n3);
    }
    float* yr = y_glob + (size_t)r * kD;
    yr[lane]      = __uint_as_float(f2tf(n0 * fast_rcp(d0)));
    yr[lane + 32] = __uint_as_float(f2tf(n1 * fast_rcp(d1)));
    yr[lane + 64] = __uint_as_float(f2tf(n2 * fast_rcp(d2)));
    yr[lane + 96] = __uint_as_float(f2tf(n3 * fast_rcp(d3)));
}

// ========================= K3: out = y@W_w^T + W_b + x0 =========================
// grid (128 B-tiles, 8 N-tiles), 256 thr. Tile 128x128, K=128 single pass.
__global__ void __launch_bounds__(256, 2)
out_kernel(const float* __restrict__ x0, const float* __restrict__ Ww,
           const float* __restrict__ Wb, float* __restrict__ out) {
    extern __shared__ uint32_t W3[];  // [128][132] tf32 bits

    const int tid  = threadIdx.x;
    const int lane = tid & 31;
    const int wid  = tid >> 5;
    const int gid  = lane >> 2;
    const int tig  = lane & 3;
    const int wm   = wid >> 1;
    const int wn   = wid & 1;
    const int row0 = blockIdx.x * 128;
    const int col0 = blockIdx.y * 128;

    // stage W rows [col0, col0+128) x 128 cols (tf32)
#pragma unroll
    for (int i = 0; i < 16; i++) {
        int idx = tid + 256 * i;     // 0..4095
        int rr = idx >> 5;           // 0..127
        int cc = idx & 31;           // float4 index 0..31
        float4 v = *reinterpret_cast<const float4*>(
            Ww + (size_t)(col0 + rr) * kD + cc * 4);
        sts_tf4(&W3[rr * kW3Str + cc * 4], v);
    }
    __syncthreads();

    float acc[2][8][4];
#pragma unroll
    for (int a = 0; a < 2; a++)
#pragma unroll
        for (int b = 0; b < 8; b++)
#pragma unroll
            for (int c = 0; c < 4; c++) acc[a][b][c] = 0.f;

    const uint32_t* ybase = reinterpret_cast<const uint32_t*>(y_glob);
#pragma unroll 4
    for (int ks = 0; ks < 16; ks++) {
        int k = ks * 8;
        uint32_t a[2][4];
#pragma unroll
        for (int mt = 0; mt < 2; mt++) {
            const uint32_t* yb =
                ybase + (size_t)(row0 + wm * 32 + mt * 16 + gid) * kD + k + tig;
            a[mt][0] = yb[0];
            a[mt][1] = yb[8 * kD];
            a[mt][2] = yb[4];
            a[mt][3] = yb[8 * kD + 4];
        }
#pragma unroll
        for (int nt = 0; nt < 8; nt++) {
            int nb = (wn * 64 + nt * 8 + gid) * kW3Str + k + tig;
            uint32_t b0 = W3[nb];
            uint32_t b1 = W3[nb + 4];
            mma_tf32(acc[0][nt], a[0], b0, b1);
            mma_tf32(acc[1][nt], a[1], b0, b1);
        }
    }

    // epilogue: + W_b + x0 residual
#pragma unroll
    for (int mt = 0; mt < 2; mt++)
#pragma unroll
        for (int nt = 0; nt < 8; nt++)
#pragma unroll
            for (int pair = 0; pair < 2; pair++) {
                int r = wm * 32 + mt * 16 + gid + pair * 8;
                int n = col0 + wn * 64 + nt * 8 + tig * 2;
                float2 xx = *reinterpret_cast<const float2*>(
                    x0 + (size_t)(row0 + r) * kC + n);
                float2 o;
                o.x = acc[mt][nt][pair * 2 + 0] + Wb[n] + xx.x;
                o.y = acc[mt][nt][pair * 2 + 1] + Wb[n + 1] + xx.y;
                *reinterpret_cast<float2*>(out + (size_t)(row0 + r) * kC + n) = o;
            }
}

extern "C" void kernel_launch(void* const* d_in, const int* in_sizes, int n_in,
                              void* d_out, int out_size) {
    (void)in_sizes; (void)n_in; (void)out_size;
    const float* x0   = (const float*)d_in[0];
    const float* x1   = (const float*)d_in[1];
    const float* g_w  = (const float*)d_in[2];
    const float* g_b  = (const float*)d_in[3];
    const float* th_w = (const float*)d_in[4];
    const float* th_b = (const float*)d_in[5];
    const float* ph_w = (const float*)d_in[6];
    const float* ph_b = (const float*)d_in[7];
    const float* Ww   = (const float*)d_in[8];
    const float* Wb   = (const float*)d_in[9];
    float* out = (float*)d_out;

    cudaFuncSetAttribute(out_kernel,
                         cudaFuncAttributeMaxDynamicSharedMemorySize, kK3Smem);

    proj_kernel<<<dim3(128, 3), 256>>>(x0, x1, g_w, g_b, th_w, th_b, ph_w, ph_b);
    attn_kernel<<<2048, 256>>>();
    out_kernel<<<dim3(128, 8), 256, kK3Smem>>>(x0, Ww, Wb, out);
}